// round 1
// baseline (speedup 1.0000x reference)
#include <cuda_runtime.h>
#include <cuda_bf16.h>
#include <math.h>

// Problem constants
#define BATCH 2
#define SEQ   2048
#define ROWS  (BATCH * SEQ)        // 4096
#define INNER 512
#define HEADS 8
#define DHEAD 64
#define QKV_N (3 * INNER)          // 1536
#define FF_N  (4 * INNER)          // 2048
#define LN_EPS 1e-6f

// ---------------------------------------------------------------------------
// Scratch (no allocations allowed -> __device__ globals)
// ---------------------------------------------------------------------------
__device__ float g_qkv [ROWS * QKV_N];   // x @ w_qkv
__device__ float g_attn[ROWS * INNER];   // attention output (b,n,inner)
__device__ float g_proj[ROWS * INNER];   // attn @ w_out + b_out
__device__ float g_res1[ROWS * INNER];   // LN(x + proj)
__device__ float g_mid [ROWS * FF_N];    // res1 @ w_ff1
__device__ float g_ff  [ROWS * INNER];   // mid @ w_ff2

// ---------------------------------------------------------------------------
// SGEMM: C[M,N] = A[M,K] @ B[K,N] (+ bias[N]), all row-major fp32.
// 128x128 block tile, BK=16, 256 threads, 8x8 per-thread microtile.
// M % 128 == 0, N % 128 == 0, K % 16 == 0 (true for all four calls).
// ---------------------------------------------------------------------------
#define BM 128
#define BN 128
#define BK 16

__global__ __launch_bounds__(256) void sgemm_kernel(
    const float* __restrict__ A, const float* __restrict__ B,
    const float* __restrict__ bias, float* __restrict__ C,
    int M, int N, int K)
{
    __shared__ float As[BK][BM];      // A tile, transposed: As[k][m]
    __shared__ float Bs[BK][BN];      // B tile: Bs[k][n]

    const int tid = threadIdx.x;
    const int bm = blockIdx.y * BM;
    const int bn = blockIdx.x * BN;

    // A load map: per float4, row = tid/4 (0..63), col4 = (tid%4)*4; 2 row batches
    const int a_r  = tid >> 2;
    const int a_c  = (tid & 3) * 4;
    // B load map: per float4, row = tid/32 (0..7), col4 = (tid%32)*4; 2 row batches
    const int b_r  = tid >> 5;
    const int b_c  = (tid & 31) * 4;

    const int tx = tid & 15;          // 0..15 -> N microtile
    const int ty = tid >> 4;          // 0..15 -> M microtile

    float acc[8][8];
#pragma unroll
    for (int i = 0; i < 8; i++)
#pragma unroll
        for (int j = 0; j < 8; j++) acc[i][j] = 0.f;

    for (int k0 = 0; k0 < K; k0 += BK) {
#pragma unroll
        for (int it = 0; it < 2; it++) {
            int r = a_r + it * 64;
            float4 v = *(const float4*)(A + (size_t)(bm + r) * K + k0 + a_c);
            As[a_c + 0][r] = v.x;
            As[a_c + 1][r] = v.y;
            As[a_c + 2][r] = v.z;
            As[a_c + 3][r] = v.w;
        }
#pragma unroll
        for (int it = 0; it < 2; it++) {
            int r = b_r + it * 8;
            *(float4*)(&Bs[r][b_c]) =
                *(const float4*)(B + (size_t)(k0 + r) * N + bn + b_c);
        }
        __syncthreads();

#pragma unroll
        for (int k = 0; k < BK; k++) {
            float ar[8], br[8];
#pragma unroll
            for (int i = 0; i < 4; i++) {
                ar[i]     = As[k][ty * 4 + i];
                ar[i + 4] = As[k][64 + ty * 4 + i];
            }
#pragma unroll
            for (int j = 0; j < 4; j++) {
                br[j]     = Bs[k][tx * 4 + j];
                br[j + 4] = Bs[k][64 + tx * 4 + j];
            }
#pragma unroll
            for (int i = 0; i < 8; i++)
#pragma unroll
                for (int j = 0; j < 8; j++)
                    acc[i][j] = fmaf(ar[i], br[j], acc[i][j]);
        }
        __syncthreads();
    }

    // Epilogue (optional bias), vectorized stores
#pragma unroll
    for (int i = 0; i < 8; i++) {
        int r = bm + ((i < 4) ? (ty * 4 + i) : (64 + ty * 4 + i - 4));
#pragma unroll
        for (int half = 0; half < 2; half++) {
            int c = bn + tx * 4 + half * 64;
            float4 v;
            int j0 = half * 4;
            if (bias) {
                v.x = acc[i][j0 + 0] + bias[c + 0];
                v.y = acc[i][j0 + 1] + bias[c + 1];
                v.z = acc[i][j0 + 2] + bias[c + 2];
                v.w = acc[i][j0 + 3] + bias[c + 3];
            } else {
                v.x = acc[i][j0 + 0];
                v.y = acc[i][j0 + 1];
                v.z = acc[i][j0 + 2];
                v.w = acc[i][j0 + 3];
            }
            *(float4*)(C + (size_t)r * N + c) = v;
        }
    }
}

// ---------------------------------------------------------------------------
// Flash attention (fp32, online softmax).
// Grid: (SEQ/64, BATCH*HEADS). Block: 256 threads.
// qkv layout per row: [q(0..511) | k(512..1023) | v(1024..1535)], head h at h*64.
// smem: Qt [d][q] (scaled), KPt: K as [d][k] then reused for P^T [k][q], Vs [k][d].
// 3 * 16KB = 48KB static smem.
// ---------------------------------------------------------------------------
__global__ __launch_bounds__(256) void attn_kernel(
    const float* __restrict__ qkv, float* __restrict__ out)
{
    __shared__ float Qt [64][64];
    __shared__ float KPt[64][64];
    __shared__ float Vs [64][64];

    const int tid = threadIdx.x;
    const int bh  = blockIdx.y;
    const int b   = bh >> 3;
    const int h   = bh & 7;
    const int q0  = blockIdx.x * 64;

    const float* base = qkv + (size_t)b * SEQ * QKV_N;
    const int qc = h * DHEAD;
    const int kc = INNER + h * DHEAD;
    const int vc = 2 * INNER + h * DHEAD;
    const float scale = 0.125f;   // 1/sqrt(64)

    const int lr  = tid >> 4;          // 0..15 (row within load batch)
    const int lc4 = (tid & 15) * 4;    // 0..60 (col, float4)

    // Load Q tile transposed (scaled once here)
#pragma unroll
    for (int it = 0; it < 4; it++) {
        int r = lr + it * 16;
        float4 v = *(const float4*)(base + (size_t)(q0 + r) * QKV_N + qc + lc4);
        Qt[lc4 + 0][r] = v.x * scale;
        Qt[lc4 + 1][r] = v.y * scale;
        Qt[lc4 + 2][r] = v.z * scale;
        Qt[lc4 + 3][r] = v.w * scale;
    }

    const int tx = tid & 15;   // key/dhead micro-col
    const int ty = tid >> 4;   // query micro-row

    float o[4][4], m[4], l[4];
#pragma unroll
    for (int i = 0; i < 4; i++) {
        m[i] = -1e30f; l[i] = 0.f;
#pragma unroll
        for (int j = 0; j < 4; j++) o[i][j] = 0.f;
    }

    for (int k0 = 0; k0 < SEQ; k0 += 64) {
        __syncthreads();   // previous iter done with KPt/Vs; Qt visible (first iter)
        // Load K transposed, V direct
#pragma unroll
        for (int it = 0; it < 4; it++) {
            int r = lr + it * 16;
            float4 kv = *(const float4*)(base + (size_t)(k0 + r) * QKV_N + kc + lc4);
            KPt[lc4 + 0][r] = kv.x;
            KPt[lc4 + 1][r] = kv.y;
            KPt[lc4 + 2][r] = kv.z;
            KPt[lc4 + 3][r] = kv.w;
            float4 vv = *(const float4*)(base + (size_t)(k0 + r) * QKV_N + vc + lc4);
            *(float4*)(&Vs[r][lc4]) = vv;
        }
        __syncthreads();

        // S = (Q*scale) @ K^T  (4x4 microtile per thread)
        float s[4][4];
#pragma unroll
        for (int i = 0; i < 4; i++)
#pragma unroll
            for (int j = 0; j < 4; j++) s[i][j] = 0.f;
#pragma unroll 8
        for (int d = 0; d < 64; d++) {
            float aq[4], bk[4];
#pragma unroll
            for (int i = 0; i < 4; i++) aq[i] = Qt[d][ty * 4 + i];
#pragma unroll
            for (int j = 0; j < 4; j++) bk[j] = KPt[d][tx * 4 + j];
#pragma unroll
            for (int i = 0; i < 4; i++)
#pragma unroll
                for (int j = 0; j < 4; j++)
                    s[i][j] = fmaf(aq[i], bk[j], s[i][j]);
        }

        // Online softmax per query row (16 threads per row = xor-closed lane group)
#pragma unroll
        for (int i = 0; i < 4; i++) {
            float rm = s[i][0];
#pragma unroll
            for (int j = 1; j < 4; j++) rm = fmaxf(rm, s[i][j]);
#pragma unroll
            for (int off = 8; off >= 1; off >>= 1)
                rm = fmaxf(rm, __shfl_xor_sync(0xffffffffu, rm, off));
            float mn = fmaxf(m[i], rm);
            float alpha = __expf(m[i] - mn);
            m[i] = mn;
            float rs = 0.f;
#pragma unroll
            for (int j = 0; j < 4; j++) {
                s[i][j] = __expf(s[i][j] - mn);
                rs += s[i][j];
            }
#pragma unroll
            for (int off = 8; off >= 1; off >>= 1)
                rs += __shfl_xor_sync(0xffffffffu, rs, off);
            l[i] = l[i] * alpha + rs;
#pragma unroll
            for (int j = 0; j < 4; j++) o[i][j] *= alpha;
        }
        __syncthreads();   // everyone done reading KPt as K

        // Store P transposed into KPt: Pt[key][query]
#pragma unroll
        for (int i = 0; i < 4; i++)
#pragma unroll
            for (int j = 0; j < 4; j++)
                KPt[tx * 4 + j][ty * 4 + i] = s[i][j];
        __syncthreads();

        // O += P @ V
#pragma unroll 8
        for (int kk = 0; kk < 64; kk++) {
            float ap[4], bv[4];
#pragma unroll
            for (int i = 0; i < 4; i++) ap[i] = KPt[kk][ty * 4 + i];
#pragma unroll
            for (int j = 0; j < 4; j++) bv[j] = Vs[kk][tx * 4 + j];
#pragma unroll
            for (int i = 0; i < 4; i++)
#pragma unroll
                for (int j = 0; j < 4; j++)
                    o[i][j] = fmaf(ap[i], bv[j], o[i][j]);
        }
    }

    // Epilogue: normalize and write to [b, q, h*64 + d]
#pragma unroll
    for (int i = 0; i < 4; i++) {
        float inv = 1.f / l[i];
        int r = q0 + ty * 4 + i;
        float4 v;
        v.x = o[i][0] * inv;
        v.y = o[i][1] * inv;
        v.z = o[i][2] * inv;
        v.w = o[i][3] * inv;
        *(float4*)(out + (size_t)(b * SEQ + r) * INNER + h * DHEAD + tx * 4) = v;
    }
}

// ---------------------------------------------------------------------------
// Fused residual + LayerNorm: out[row] = LN(A[row] + B[row]) * g + be
// One block (128 threads) per row of 512 elements.
// ---------------------------------------------------------------------------
__global__ __launch_bounds__(128) void ln_res_kernel(
    const float* __restrict__ A, const float* __restrict__ B,
    const float* __restrict__ g, const float* __restrict__ be,
    float* __restrict__ out)
{
    const int row = blockIdx.x;
    const int tid = threadIdx.x;
    const size_t off = (size_t)row * INNER + tid * 4;

    float4 va = *(const float4*)(A + off);
    float4 vb = *(const float4*)(B + off);
    float x0 = va.x + vb.x, x1 = va.y + vb.y, x2 = va.z + vb.z, x3 = va.w + vb.w;

    float s  = x0 + x1 + x2 + x3;
    float s2 = x0 * x0 + x1 * x1 + x2 * x2 + x3 * x3;
#pragma unroll
    for (int o2 = 16; o2 >= 1; o2 >>= 1) {
        s  += __shfl_xor_sync(0xffffffffu, s,  o2);
        s2 += __shfl_xor_sync(0xffffffffu, s2, o2);
    }
    __shared__ float sh[8];
    int w = tid >> 5;
    if ((tid & 31) == 0) { sh[w] = s; sh[4 + w] = s2; }
    __syncthreads();
    s  = sh[0] + sh[1] + sh[2] + sh[3];
    s2 = sh[4] + sh[5] + sh[6] + sh[7];

    const float inv_n = 1.f / (float)INNER;
    float mu   = s * inv_n;
    float var  = s2 * inv_n - mu * mu;
    float rstd = rsqrtf(var + LN_EPS);

    float4 vg  = *(const float4*)(g  + tid * 4);
    float4 vbe = *(const float4*)(be + tid * 4);
    float4 vo;
    vo.x = (x0 - mu) * rstd * vg.x + vbe.x;
    vo.y = (x1 - mu) * rstd * vg.y + vbe.y;
    vo.z = (x2 - mu) * rstd * vg.z + vbe.z;
    vo.w = (x3 - mu) * rstd * vg.w + vbe.w;
    *(float4*)(out + off) = vo;
}

// ---------------------------------------------------------------------------
// Launch
// ---------------------------------------------------------------------------
extern "C" void kernel_launch(void* const* d_in, const int* in_sizes, int n_in,
                              void* d_out, int out_size)
{
    const float* x     = (const float*)d_in[0];
    const float* w_qkv = (const float*)d_in[1];
    const float* w_out = (const float*)d_in[2];
    const float* b_out = (const float*)d_in[3];
    const float* w_ff1 = (const float*)d_in[4];
    const float* w_ff2 = (const float*)d_in[5];
    const float* g1    = (const float*)d_in[6];
    const float* be1   = (const float*)d_in[7];
    const float* g2    = (const float*)d_in[8];
    const float* be2   = (const float*)d_in[9];
    float* out = (float*)d_out;

    float *qkv, *attn, *proj, *res1, *mid, *ff;
    cudaGetSymbolAddress((void**)&qkv,  g_qkv);
    cudaGetSymbolAddress((void**)&attn, g_attn);
    cudaGetSymbolAddress((void**)&proj, g_proj);
    cudaGetSymbolAddress((void**)&res1, g_res1);
    cudaGetSymbolAddress((void**)&mid,  g_mid);
    cudaGetSymbolAddress((void**)&ff,   g_ff);

    // 1) qkv = x @ w_qkv                       [4096,512] x [512,1536]
    sgemm_kernel<<<dim3(QKV_N / BN, ROWS / BM), 256>>>(x, w_qkv, nullptr, qkv,
                                                       ROWS, QKV_N, INNER);
    // 2) attention
    attn_kernel<<<dim3(SEQ / 64, BATCH * HEADS), 256>>>(qkv, attn);
    // 3) proj = attn @ w_out + b_out           [4096,512] x [512,512]
    sgemm_kernel<<<dim3(INNER / BN, ROWS / BM), 256>>>(attn, w_out, b_out, proj,
                                                       ROWS, INNER, INNER);
    // 4) res1 = LN(x + proj)
    ln_res_kernel<<<ROWS, 128>>>(x, proj, g1, be1, res1);
    // 5) mid = res1 @ w_ff1                    [4096,512] x [512,2048]
    sgemm_kernel<<<dim3(FF_N / BN, ROWS / BM), 256>>>(res1, w_ff1, nullptr, mid,
                                                      ROWS, FF_N, INNER);
    // 6) ff = mid @ w_ff2                      [4096,2048] x [2048,512]
    sgemm_kernel<<<dim3(INNER / BN, ROWS / BM), 256>>>(mid, w_ff2, nullptr, ff,
                                                       ROWS, INNER, FF_N);
    // 7) out = LN(res1 + ff)
    ln_res_kernel<<<ROWS, 128>>>(res1, ff, g2, be2, out);
}

// round 2
// speedup vs baseline: 1.4098x; 1.4098x over previous
#include <cuda_runtime.h>
#include <cuda_bf16.h>
#include <math.h>
#include <stdint.h>

// Problem constants
#define BATCH 2
#define SEQ   2048
#define ROWS  (BATCH * SEQ)        // 4096
#define INNER 512
#define HEADS 8
#define DHEAD 64
#define QKV_N (3 * INNER)          // 1536
#define FF_N  (4 * INNER)          // 2048
#define LN_EPS 1e-6f

// ---------------------------------------------------------------------------
// Scratch (no allocations allowed -> __device__ globals)
// ---------------------------------------------------------------------------
__device__ float g_qkv [ROWS * QKV_N];   // x @ w_qkv
__device__ float g_attn[ROWS * INNER];   // attention output (b,n,inner)
__device__ float g_proj[ROWS * INNER];   // attn @ w_out + b_out
__device__ float g_res1[ROWS * INNER];   // LN(x + proj)
__device__ float g_mid [ROWS * FF_N];    // res1 @ w_ff1
__device__ float g_ff  [ROWS * INNER];   // mid @ w_ff2

// split-bf16 staging buffers (reused across GEMMs; graph is sequential)
__device__ __nv_bfloat16 g_ah[ROWS * FF_N];   // activations hi (max 4096x2048)
__device__ __nv_bfloat16 g_al[ROWS * FF_N];   // activations lo
__device__ __nv_bfloat16 g_bh[FF_N * INNER];  // weights hi (max 2048x512 / 512x1536 < 1M)
__device__ __nv_bfloat16 g_bl[FF_N * INNER];  // weights lo

// ---------------------------------------------------------------------------
// fp32 -> (hi, lo) bf16 split.  x = hi + lo + O(2^-17 * x)
// ---------------------------------------------------------------------------
__global__ __launch_bounds__(256) void cvt_split_kernel(
    const float4* __restrict__ x, uint2* __restrict__ hi, uint2* __restrict__ lo,
    int n4)
{
    int i = blockIdx.x * blockDim.x + threadIdx.x;
    if (i >= n4) return;
    float4 v = x[i];
    union { __nv_bfloat16 b[4]; uint2 u; } H, L;
    H.b[0] = __float2bfloat16(v.x);
    H.b[1] = __float2bfloat16(v.y);
    H.b[2] = __float2bfloat16(v.z);
    H.b[3] = __float2bfloat16(v.w);
    L.b[0] = __float2bfloat16(v.x - __bfloat162float(H.b[0]));
    L.b[1] = __float2bfloat16(v.y - __bfloat162float(H.b[1]));
    L.b[2] = __float2bfloat16(v.z - __bfloat162float(H.b[2]));
    L.b[3] = __float2bfloat16(v.w - __bfloat162float(H.b[3]));
    hi[i] = H.u;
    lo[i] = L.u;
}

// ---------------------------------------------------------------------------
// Tensor-core GEMM on split-bf16 operands, fp32 accumulate:
//   C = Ah@Bh + Ah@Bl + Al@Bh (+bias)
// 128x128x32 block tile, 256 threads (8 warps as 2M x 4N), warp tile 64x32.
// mma.sync.m16n8k16.bf16 + ldmatrix with XOR swizzles (conflict-free).
// M%128==0, N%128==0, K%32==0.
// ---------------------------------------------------------------------------
__device__ __forceinline__ void ldsm_x4(uint32_t& r0, uint32_t& r1,
                                        uint32_t& r2, uint32_t& r3, uint32_t addr)
{
    asm volatile("ldmatrix.sync.aligned.m8n8.x4.shared.b16 {%0,%1,%2,%3}, [%4];"
                 : "=r"(r0), "=r"(r1), "=r"(r2), "=r"(r3) : "r"(addr));
}
__device__ __forceinline__ void ldsm_x2t(uint32_t& r0, uint32_t& r1, uint32_t addr)
{
    asm volatile("ldmatrix.sync.aligned.m8n8.x2.trans.shared.b16 {%0,%1}, [%2];"
                 : "=r"(r0), "=r"(r1) : "r"(addr));
}
__device__ __forceinline__ void mma_bf16(float* c, const uint32_t* a, const uint32_t* b)
{
    asm volatile(
        "mma.sync.aligned.m16n8k16.row.col.f32.bf16.bf16.f32 "
        "{%0,%1,%2,%3}, {%4,%5,%6,%7}, {%8,%9}, {%0,%1,%2,%3};"
        : "+f"(c[0]), "+f"(c[1]), "+f"(c[2]), "+f"(c[3])
        : "r"(a[0]), "r"(a[1]), "r"(a[2]), "r"(a[3]), "r"(b[0]), "r"(b[1]));
}

__global__ __launch_bounds__(256) void hgemm_split_kernel(
    const __nv_bfloat16* __restrict__ Ah, const __nv_bfloat16* __restrict__ Al,
    const __nv_bfloat16* __restrict__ Bh, const __nv_bfloat16* __restrict__ Bl,
    const float* __restrict__ bias, float* __restrict__ C,
    int M, int N, int K)
{
    // smem in uint4 (16B = 8 bf16 "chunks"); [hl][...]
    __shared__ uint4 sA[2][512];   // 128 rows x 4 chunks
    __shared__ uint4 sB[2][512];   // 32 rows x 16 chunks

    const int tid  = threadIdx.x;
    const int lane = tid & 31;
    const int warp = tid >> 5;
    const int wm   = warp >> 2;    // 0..1
    const int wn   = warp & 3;     // 0..3
    const int bm   = blockIdx.y * 128;
    const int bn   = blockIdx.x * 128;

    // gmem->smem load maps
    const int arow = tid >> 2;           // 0..63 (+64 second batch)
    const int ach  = tid & 3;            // A chunk 0..3
    const int brow = tid >> 4;           // 0..15 (+16 second batch)
    const int bch  = tid & 15;           // B chunk 0..15

    const int aSwS = ach ^ ((arow >> 1) & 3);     // store swizzle (same both halves)
    const int bSwS = bch ^ (brow & 7);

    // ldmatrix per-lane address components
    const uint32_t aBase = (uint32_t)__cvta_generic_to_shared(&sA[0][0]);
    const uint32_t bBase = (uint32_t)__cvta_generic_to_shared(&sB[0][0]);
    const int ar   = wm * 64 + (lane & 15);
    const int aSw  = (ar >> 1) & 3;
    const int aHi  = lane >> 4;          // 0/1: second k8 chunk
    const int br   = lane & 15;
    const int bSw  = br & 7;

    float acc[4][4][4];
#pragma unroll
    for (int i = 0; i < 4; i++)
#pragma unroll
        for (int j = 0; j < 4; j++)
#pragma unroll
            for (int r = 0; r < 4; r++) acc[i][j][r] = 0.f;

    uint4 rA[2][2], rB[2][2];
    // prefetch k0 = 0
    {
        const int kk = 0;
        rA[0][0] = *(const uint4*)(Ah + (size_t)(bm + arow)      * K + kk + ach * 8);
        rA[0][1] = *(const uint4*)(Ah + (size_t)(bm + arow + 64) * K + kk + ach * 8);
        rA[1][0] = *(const uint4*)(Al + (size_t)(bm + arow)      * K + kk + ach * 8);
        rA[1][1] = *(const uint4*)(Al + (size_t)(bm + arow + 64) * K + kk + ach * 8);
        rB[0][0] = *(const uint4*)(Bh + (size_t)(kk + brow)      * N + bn + bch * 8);
        rB[0][1] = *(const uint4*)(Bh + (size_t)(kk + brow + 16) * N + bn + bch * 8);
        rB[1][0] = *(const uint4*)(Bl + (size_t)(kk + brow)      * N + bn + bch * 8);
        rB[1][1] = *(const uint4*)(Bl + (size_t)(kk + brow + 16) * N + bn + bch * 8);
    }

    const int sa0 = arow * 4 + aSwS;
    const int sa1 = (arow + 64) * 4 + aSwS;
    const int sb0 = brow * 16 + bSwS;
    const int sb1 = (brow + 16) * 16 + bSwS;

    for (int k0 = 0; k0 < K; k0 += 32) {
        __syncthreads();
        sA[0][sa0] = rA[0][0]; sA[0][sa1] = rA[0][1];
        sA[1][sa0] = rA[1][0]; sA[1][sa1] = rA[1][1];
        sB[0][sb0] = rB[0][0]; sB[0][sb1] = rB[0][1];
        sB[1][sb0] = rB[1][0]; sB[1][sb1] = rB[1][1];
        __syncthreads();

        // prefetch next tile (dummy-reload k=0 on last iter)
        {
            int kk = k0 + 32; if (kk >= K) kk = 0;
            rA[0][0] = *(const uint4*)(Ah + (size_t)(bm + arow)      * K + kk + ach * 8);
            rA[0][1] = *(const uint4*)(Ah + (size_t)(bm + arow + 64) * K + kk + ach * 8);
            rA[1][0] = *(const uint4*)(Al + (size_t)(bm + arow)      * K + kk + ach * 8);
            rA[1][1] = *(const uint4*)(Al + (size_t)(bm + arow + 64) * K + kk + ach * 8);
            rB[0][0] = *(const uint4*)(Bh + (size_t)(kk + brow)      * N + bn + bch * 8);
            rB[0][1] = *(const uint4*)(Bh + (size_t)(kk + brow + 16) * N + bn + bch * 8);
            rB[1][0] = *(const uint4*)(Bl + (size_t)(kk + brow)      * N + bn + bch * 8);
            rB[1][1] = *(const uint4*)(Bl + (size_t)(kk + brow + 16) * N + bn + bch * 8);
        }

#pragma unroll
        for (int s = 0; s < 2; s++) {
            uint32_t Af[2][4][4];   // [hl][mtile][reg]
            uint32_t Bf[2][4][2];   // [hl][ntile][reg]
#pragma unroll
            for (int hl = 0; hl < 2; hl++) {
#pragma unroll
                for (int i = 0; i < 4; i++) {
                    uint32_t addr = aBase + (uint32_t)(hl * 8192 +
                        (ar + i * 16) * 64 + (((2 * s + aHi) ^ aSw) * 16));
                    ldsm_x4(Af[hl][i][0], Af[hl][i][1], Af[hl][i][2], Af[hl][i][3], addr);
                }
#pragma unroll
                for (int j = 0; j < 4; j++) {
                    uint32_t addr = bBase + (uint32_t)(hl * 8192 +
                        (s * 16 + br) * 256 + ((((wn << 2) + j) ^ bSw) * 16));
                    ldsm_x2t(Bf[hl][j][0], Bf[hl][j][1], addr);
                }
            }
#pragma unroll
            for (int i = 0; i < 4; i++) {
#pragma unroll
                for (int j = 0; j < 4; j++) {
                    mma_bf16(acc[i][j], Af[0][i], Bf[0][j]);   // hh
                    mma_bf16(acc[i][j], Af[0][i], Bf[1][j]);   // hl
                    mma_bf16(acc[i][j], Af[1][i], Bf[0][j]);   // lh
                }
            }
        }
    }

    // Epilogue: fragment m16n8 -> C (+bias)
    const int grp = lane >> 2;
    const int qc  = (lane & 3) * 2;
#pragma unroll
    for (int i = 0; i < 4; i++) {
#pragma unroll
        for (int j = 0; j < 4; j++) {
            int row = bm + wm * 64 + i * 16 + grp;
            int col = bn + wn * 32 + j * 8 + qc;
            float b0 = 0.f, b1 = 0.f;
            if (bias) { b0 = bias[col]; b1 = bias[col + 1]; }
            float2 v0 = make_float2(acc[i][j][0] + b0, acc[i][j][1] + b1);
            float2 v1 = make_float2(acc[i][j][2] + b0, acc[i][j][3] + b1);
            *(float2*)(C + (size_t)row * N + col)       = v0;
            *(float2*)(C + (size_t)(row + 8) * N + col) = v1;
        }
    }
}

// ---------------------------------------------------------------------------
// Flash attention (fp32, online softmax) — unchanged from round 1.
// ---------------------------------------------------------------------------
__global__ __launch_bounds__(256) void attn_kernel(
    const float* __restrict__ qkv, float* __restrict__ out)
{
    __shared__ float Qt [64][64];
    __shared__ float KPt[64][64];
    __shared__ float Vs [64][64];

    const int tid = threadIdx.x;
    const int bh  = blockIdx.y;
    const int b   = bh >> 3;
    const int h   = bh & 7;
    const int q0  = blockIdx.x * 64;

    const float* base = qkv + (size_t)b * SEQ * QKV_N;
    const int qc = h * DHEAD;
    const int kc = INNER + h * DHEAD;
    const int vc = 2 * INNER + h * DHEAD;
    const float scale = 0.125f;

    const int lr  = tid >> 4;
    const int lc4 = (tid & 15) * 4;

#pragma unroll
    for (int it = 0; it < 4; it++) {
        int r = lr + it * 16;
        float4 v = *(const float4*)(base + (size_t)(q0 + r) * QKV_N + qc + lc4);
        Qt[lc4 + 0][r] = v.x * scale;
        Qt[lc4 + 1][r] = v.y * scale;
        Qt[lc4 + 2][r] = v.z * scale;
        Qt[lc4 + 3][r] = v.w * scale;
    }

    const int tx = tid & 15;
    const int ty = tid >> 4;

    float o[4][4], m[4], l[4];
#pragma unroll
    for (int i = 0; i < 4; i++) {
        m[i] = -1e30f; l[i] = 0.f;
#pragma unroll
        for (int j = 0; j < 4; j++) o[i][j] = 0.f;
    }

    for (int k0 = 0; k0 < SEQ; k0 += 64) {
        __syncthreads();
#pragma unroll
        for (int it = 0; it < 4; it++) {
            int r = lr + it * 16;
            float4 kv = *(const float4*)(base + (size_t)(k0 + r) * QKV_N + kc + lc4);
            KPt[lc4 + 0][r] = kv.x;
            KPt[lc4 + 1][r] = kv.y;
            KPt[lc4 + 2][r] = kv.z;
            KPt[lc4 + 3][r] = kv.w;
            float4 vv = *(const float4*)(base + (size_t)(k0 + r) * QKV_N + vc + lc4);
            *(float4*)(&Vs[r][lc4]) = vv;
        }
        __syncthreads();

        float s[4][4];
#pragma unroll
        for (int i = 0; i < 4; i++)
#pragma unroll
            for (int j = 0; j < 4; j++) s[i][j] = 0.f;
#pragma unroll 8
        for (int d = 0; d < 64; d++) {
            float aq[4], bk[4];
#pragma unroll
            for (int i = 0; i < 4; i++) aq[i] = Qt[d][ty * 4 + i];
#pragma unroll
            for (int j = 0; j < 4; j++) bk[j] = KPt[d][tx * 4 + j];
#pragma unroll
            for (int i = 0; i < 4; i++)
#pragma unroll
                for (int j = 0; j < 4; j++)
                    s[i][j] = fmaf(aq[i], bk[j], s[i][j]);
        }

#pragma unroll
        for (int i = 0; i < 4; i++) {
            float rm = s[i][0];
#pragma unroll
            for (int j = 1; j < 4; j++) rm = fmaxf(rm, s[i][j]);
#pragma unroll
            for (int off = 8; off >= 1; off >>= 1)
                rm = fmaxf(rm, __shfl_xor_sync(0xffffffffu, rm, off));
            float mn = fmaxf(m[i], rm);
            float alpha = __expf(m[i] - mn);
            m[i] = mn;
            float rs = 0.f;
#pragma unroll
            for (int j = 0; j < 4; j++) {
                s[i][j] = __expf(s[i][j] - mn);
                rs += s[i][j];
            }
#pragma unroll
            for (int off = 8; off >= 1; off >>= 1)
                rs += __shfl_xor_sync(0xffffffffu, rs, off);
            l[i] = l[i] * alpha + rs;
#pragma unroll
            for (int j = 0; j < 4; j++) o[i][j] *= alpha;
        }
        __syncthreads();

#pragma unroll
        for (int i = 0; i < 4; i++)
#pragma unroll
            for (int j = 0; j < 4; j++)
                KPt[tx * 4 + j][ty * 4 + i] = s[i][j];
        __syncthreads();

#pragma unroll 8
        for (int kk = 0; kk < 64; kk++) {
            float ap[4], bv[4];
#pragma unroll
            for (int i = 0; i < 4; i++) ap[i] = KPt[kk][ty * 4 + i];
#pragma unroll
            for (int j = 0; j < 4; j++) bv[j] = Vs[kk][tx * 4 + j];
#pragma unroll
            for (int i = 0; i < 4; i++)
#pragma unroll
                for (int j = 0; j < 4; j++)
                    o[i][j] = fmaf(ap[i], bv[j], o[i][j]);
        }
    }

#pragma unroll
    for (int i = 0; i < 4; i++) {
        float inv = 1.f / l[i];
        int r = q0 + ty * 4 + i;
        float4 v;
        v.x = o[i][0] * inv;
        v.y = o[i][1] * inv;
        v.z = o[i][2] * inv;
        v.w = o[i][3] * inv;
        *(float4*)(out + (size_t)(b * SEQ + r) * INNER + h * DHEAD + tx * 4) = v;
    }
}

// ---------------------------------------------------------------------------
// Fused residual + LayerNorm: out[row] = LN(A[row] + B[row]) * g + be
// ---------------------------------------------------------------------------
__global__ __launch_bounds__(128) void ln_res_kernel(
    const float* __restrict__ A, const float* __restrict__ B,
    const float* __restrict__ g, const float* __restrict__ be,
    float* __restrict__ out)
{
    const int row = blockIdx.x;
    const int tid = threadIdx.x;
    const size_t off = (size_t)row * INNER + tid * 4;

    float4 va = *(const float4*)(A + off);
    float4 vb = *(const float4*)(B + off);
    float x0 = va.x + vb.x, x1 = va.y + vb.y, x2 = va.z + vb.z, x3 = va.w + vb.w;

    float s  = x0 + x1 + x2 + x3;
    float s2 = x0 * x0 + x1 * x1 + x2 * x2 + x3 * x3;
#pragma unroll
    for (int o2 = 16; o2 >= 1; o2 >>= 1) {
        s  += __shfl_xor_sync(0xffffffffu, s,  o2);
        s2 += __shfl_xor_sync(0xffffffffu, s2, o2);
    }
    __shared__ float sh[8];
    int w = tid >> 5;
    if ((tid & 31) == 0) { sh[w] = s; sh[4 + w] = s2; }
    __syncthreads();
    s  = sh[0] + sh[1] + sh[2] + sh[3];
    s2 = sh[4] + sh[5] + sh[6] + sh[7];

    const float inv_n = 1.f / (float)INNER;
    float mu   = s * inv_n;
    float var  = s2 * inv_n - mu * mu;
    float rstd = rsqrtf(var + LN_EPS);

    float4 vg  = *(const float4*)(g  + tid * 4);
    float4 vbe = *(const float4*)(be + tid * 4);
    float4 vo;
    vo.x = (x0 - mu) * rstd * vg.x + vbe.x;
    vo.y = (x1 - mu) * rstd * vg.y + vbe.y;
    vo.z = (x2 - mu) * rstd * vg.z + vbe.z;
    vo.w = (x3 - mu) * rstd * vg.w + vbe.w;
    *(float4*)(out + off) = vo;
}

// ---------------------------------------------------------------------------
// Launch
// ---------------------------------------------------------------------------
static inline void cvt(const float* src, __nv_bfloat16* hi, __nv_bfloat16* lo, int n)
{
    int n4 = n / 4;
    cvt_split_kernel<<<(n4 + 255) / 256, 256>>>(
        (const float4*)src, (uint2*)hi, (uint2*)lo, n4);
}

extern "C" void kernel_launch(void* const* d_in, const int* in_sizes, int n_in,
                              void* d_out, int out_size)
{
    const float* x     = (const float*)d_in[0];
    const float* w_qkv = (const float*)d_in[1];
    const float* w_out = (const float*)d_in[2];
    const float* b_out = (const float*)d_in[3];
    const float* w_ff1 = (const float*)d_in[4];
    const float* w_ff2 = (const float*)d_in[5];
    const float* g1    = (const float*)d_in[6];
    const float* be1   = (const float*)d_in[7];
    const float* g2    = (const float*)d_in[8];
    const float* be2   = (const float*)d_in[9];
    float* out = (float*)d_out;

    float *qkv, *attn, *proj, *res1, *mid, *ff;
    __nv_bfloat16 *ah, *al, *bh, *bl;
    cudaGetSymbolAddress((void**)&qkv,  g_qkv);
    cudaGetSymbolAddress((void**)&attn, g_attn);
    cudaGetSymbolAddress((void**)&proj, g_proj);
    cudaGetSymbolAddress((void**)&res1, g_res1);
    cudaGetSymbolAddress((void**)&mid,  g_mid);
    cudaGetSymbolAddress((void**)&ff,   g_ff);
    cudaGetSymbolAddress((void**)&ah,   g_ah);
    cudaGetSymbolAddress((void**)&al,   g_al);
    cudaGetSymbolAddress((void**)&bh,   g_bh);
    cudaGetSymbolAddress((void**)&bl,   g_bl);

    // 1) qkv = x @ w_qkv
    cvt(x, ah, al, ROWS * INNER);
    cvt(w_qkv, bh, bl, INNER * QKV_N);
    hgemm_split_kernel<<<dim3(QKV_N / 128, ROWS / 128), 256>>>(
        ah, al, bh, bl, nullptr, qkv, ROWS, QKV_N, INNER);

    // 2) attention (fp32)
    attn_kernel<<<dim3(SEQ / 64, BATCH * HEADS), 256>>>(qkv, attn);

    // 3) proj = attn @ w_out + b_out
    cvt(attn, ah, al, ROWS * INNER);
    cvt(w_out, bh, bl, INNER * INNER);
    hgemm_split_kernel<<<dim3(INNER / 128, ROWS / 128), 256>>>(
        ah, al, bh, bl, b_out, proj, ROWS, INNER, INNER);

    // 4) res1 = LN(x + proj)
    ln_res_kernel<<<ROWS, 128>>>(x, proj, g1, be1, res1);

    // 5) mid = res1 @ w_ff1
    cvt(res1, ah, al, ROWS * INNER);
    cvt(w_ff1, bh, bl, INNER * FF_N);
    hgemm_split_kernel<<<dim3(FF_N / 128, ROWS / 128), 256>>>(
        ah, al, bh, bl, nullptr, mid, ROWS, FF_N, INNER);

    // 6) ff = mid @ w_ff2
    cvt(mid, ah, al, ROWS * FF_N);
    cvt(w_ff2, bh, bl, FF_N * INNER);
    hgemm_split_kernel<<<dim3(INNER / 128, ROWS / 128), 256>>>(
        ah, al, bh, bl, nullptr, ff, ROWS, INNER, FF_N);

    // 7) out = LN(res1 + ff)
    ln_res_kernel<<<ROWS, 128>>>(res1, ff, g2, be2, out);
}

// round 3
// speedup vs baseline: 2.8817x; 2.0440x over previous
#include <cuda_runtime.h>
#include <cuda_bf16.h>
#include <math.h>
#include <stdint.h>

// Problem constants
#define BATCH 2
#define SEQ   2048
#define ROWS  (BATCH * SEQ)        // 4096
#define INNER 512
#define HEADS 8
#define DHEAD 64
#define QKV_N (3 * INNER)          // 1536
#define FF_N  (4 * INNER)          // 2048
#define LN_EPS 1e-6f

// ---------------------------------------------------------------------------
// Scratch (no allocations allowed -> __device__ globals)
// ---------------------------------------------------------------------------
__device__ float g_qkv [ROWS * QKV_N];
__device__ float g_attn[ROWS * INNER];
__device__ float g_proj[ROWS * INNER];
__device__ float g_res1[ROWS * INNER];
__device__ float g_mid [ROWS * FF_N];
__device__ float g_ff  [ROWS * INNER];

__device__ __nv_bfloat16 g_ah[ROWS * FF_N];
__device__ __nv_bfloat16 g_al[ROWS * FF_N];
__device__ __nv_bfloat16 g_bh[FF_N * INNER];
__device__ __nv_bfloat16 g_bl[FF_N * INNER];

// ---------------------------------------------------------------------------
// Common PTX helpers
// ---------------------------------------------------------------------------
__device__ __forceinline__ void ldsm_x4(uint32_t& r0, uint32_t& r1,
                                        uint32_t& r2, uint32_t& r3, uint32_t addr)
{
    asm volatile("ldmatrix.sync.aligned.m8n8.x4.shared.b16 {%0,%1,%2,%3}, [%4];"
                 : "=r"(r0), "=r"(r1), "=r"(r2), "=r"(r3) : "r"(addr));
}
__device__ __forceinline__ void ldsm_x2t(uint32_t& r0, uint32_t& r1, uint32_t addr)
{
    asm volatile("ldmatrix.sync.aligned.m8n8.x2.trans.shared.b16 {%0,%1}, [%2];"
                 : "=r"(r0), "=r"(r1) : "r"(addr));
}
__device__ __forceinline__ void mma_bf16(float* c, const uint32_t* a, const uint32_t* b)
{
    asm volatile(
        "mma.sync.aligned.m16n8k16.row.col.f32.bf16.bf16.f32 "
        "{%0,%1,%2,%3}, {%4,%5,%6,%7}, {%8,%9}, {%0,%1,%2,%3};"
        : "+f"(c[0]), "+f"(c[1]), "+f"(c[2]), "+f"(c[3])
        : "r"(a[0]), "r"(a[1]), "r"(a[2]), "r"(a[3]), "r"(b[0]), "r"(b[1]));
}
__device__ __forceinline__ uint32_t packbf2(float a, float b)
{
    __nv_bfloat162 t = __floats2bfloat162_rn(a, b);   // .x=a(low), .y=b(high)
    return *reinterpret_cast<uint32_t*>(&t);
}
// split f into hi+lo bf16 pair packed (low = a-part)
__device__ __forceinline__ void split2(float a, float b, uint32_t& hi, uint32_t& lo)
{
    __nv_bfloat16 ha = __float2bfloat16(a);
    __nv_bfloat16 hb = __float2bfloat16(b);
    __nv_bfloat16 la = __float2bfloat16(a - __bfloat162float(ha));
    __nv_bfloat16 lb = __float2bfloat16(b - __bfloat162float(hb));
    __nv_bfloat162 H; H.x = ha; H.y = hb;
    __nv_bfloat162 L; L.x = la; L.y = lb;
    hi = *reinterpret_cast<uint32_t*>(&H);
    lo = *reinterpret_cast<uint32_t*>(&L);
}

// ---------------------------------------------------------------------------
// fp32 -> (hi, lo) bf16 split (bulk, for GEMM operands)
// ---------------------------------------------------------------------------
__global__ __launch_bounds__(256) void cvt_split_kernel(
    const float4* __restrict__ x, uint2* __restrict__ hi, uint2* __restrict__ lo,
    int n4)
{
    int i = blockIdx.x * blockDim.x + threadIdx.x;
    if (i >= n4) return;
    float4 v = x[i];
    union { __nv_bfloat16 b[4]; uint2 u; } H, L;
    H.b[0] = __float2bfloat16(v.x);
    H.b[1] = __float2bfloat16(v.y);
    H.b[2] = __float2bfloat16(v.z);
    H.b[3] = __float2bfloat16(v.w);
    L.b[0] = __float2bfloat16(v.x - __bfloat162float(H.b[0]));
    L.b[1] = __float2bfloat16(v.y - __bfloat162float(H.b[1]));
    L.b[2] = __float2bfloat16(v.z - __bfloat162float(H.b[2]));
    L.b[3] = __float2bfloat16(v.w - __bfloat162float(H.b[3]));
    hi[i] = H.u;
    lo[i] = L.u;
}

// ---------------------------------------------------------------------------
// Tensor-core split-bf16 GEMM (unchanged from round 2)
// ---------------------------------------------------------------------------
__global__ __launch_bounds__(256) void hgemm_split_kernel(
    const __nv_bfloat16* __restrict__ Ah, const __nv_bfloat16* __restrict__ Al,
    const __nv_bfloat16* __restrict__ Bh, const __nv_bfloat16* __restrict__ Bl,
    const float* __restrict__ bias, float* __restrict__ C,
    int M, int N, int K)
{
    __shared__ uint4 sA[2][512];
    __shared__ uint4 sB[2][512];

    const int tid  = threadIdx.x;
    const int lane = tid & 31;
    const int warp = tid >> 5;
    const int wm   = warp >> 2;
    const int wn   = warp & 3;
    const int bm   = blockIdx.y * 128;
    const int bn   = blockIdx.x * 128;

    const int arow = tid >> 2;
    const int ach  = tid & 3;
    const int brow = tid >> 4;
    const int bch  = tid & 15;

    const int aSwS = ach ^ ((arow >> 1) & 3);
    const int bSwS = bch ^ (brow & 7);

    const uint32_t aBase = (uint32_t)__cvta_generic_to_shared(&sA[0][0]);
    const uint32_t bBase = (uint32_t)__cvta_generic_to_shared(&sB[0][0]);
    const int ar   = wm * 64 + (lane & 15);
    const int aSw  = (ar >> 1) & 3;
    const int aHi  = lane >> 4;
    const int br   = lane & 15;
    const int bSw  = br & 7;

    float acc[4][4][4];
#pragma unroll
    for (int i = 0; i < 4; i++)
#pragma unroll
        for (int j = 0; j < 4; j++)
#pragma unroll
            for (int r = 0; r < 4; r++) acc[i][j][r] = 0.f;

    uint4 rA[2][2], rB[2][2];
    {
        const int kk = 0;
        rA[0][0] = *(const uint4*)(Ah + (size_t)(bm + arow)      * K + kk + ach * 8);
        rA[0][1] = *(const uint4*)(Ah + (size_t)(bm + arow + 64) * K + kk + ach * 8);
        rA[1][0] = *(const uint4*)(Al + (size_t)(bm + arow)      * K + kk + ach * 8);
        rA[1][1] = *(const uint4*)(Al + (size_t)(bm + arow + 64) * K + kk + ach * 8);
        rB[0][0] = *(const uint4*)(Bh + (size_t)(kk + brow)      * N + bn + bch * 8);
        rB[0][1] = *(const uint4*)(Bh + (size_t)(kk + brow + 16) * N + bn + bch * 8);
        rB[1][0] = *(const uint4*)(Bl + (size_t)(kk + brow)      * N + bn + bch * 8);
        rB[1][1] = *(const uint4*)(Bl + (size_t)(kk + brow + 16) * N + bn + bch * 8);
    }

    const int sa0 = arow * 4 + aSwS;
    const int sa1 = (arow + 64) * 4 + aSwS;
    const int sb0 = brow * 16 + bSwS;
    const int sb1 = (brow + 16) * 16 + bSwS;

    for (int k0 = 0; k0 < K; k0 += 32) {
        __syncthreads();
        sA[0][sa0] = rA[0][0]; sA[0][sa1] = rA[0][1];
        sA[1][sa0] = rA[1][0]; sA[1][sa1] = rA[1][1];
        sB[0][sb0] = rB[0][0]; sB[0][sb1] = rB[0][1];
        sB[1][sb0] = rB[1][0]; sB[1][sb1] = rB[1][1];
        __syncthreads();

        {
            int kk = k0 + 32; if (kk >= K) kk = 0;
            rA[0][0] = *(const uint4*)(Ah + (size_t)(bm + arow)      * K + kk + ach * 8);
            rA[0][1] = *(const uint4*)(Ah + (size_t)(bm + arow + 64) * K + kk + ach * 8);
            rA[1][0] = *(const uint4*)(Al + (size_t)(bm + arow)      * K + kk + ach * 8);
            rA[1][1] = *(const uint4*)(Al + (size_t)(bm + arow + 64) * K + kk + ach * 8);
            rB[0][0] = *(const uint4*)(Bh + (size_t)(kk + brow)      * N + bn + bch * 8);
            rB[0][1] = *(const uint4*)(Bh + (size_t)(kk + brow + 16) * N + bn + bch * 8);
            rB[1][0] = *(const uint4*)(Bl + (size_t)(kk + brow)      * N + bn + bch * 8);
            rB[1][1] = *(const uint4*)(Bl + (size_t)(kk + brow + 16) * N + bn + bch * 8);
        }

#pragma unroll
        for (int s = 0; s < 2; s++) {
            uint32_t Af[2][4][4];
            uint32_t Bf[2][4][2];
#pragma unroll
            for (int hl = 0; hl < 2; hl++) {
#pragma unroll
                for (int i = 0; i < 4; i++) {
                    uint32_t addr = aBase + (uint32_t)(hl * 8192 +
                        (ar + i * 16) * 64 + (((2 * s + aHi) ^ aSw) * 16));
                    ldsm_x4(Af[hl][i][0], Af[hl][i][1], Af[hl][i][2], Af[hl][i][3], addr);
                }
#pragma unroll
                for (int j = 0; j < 4; j++) {
                    uint32_t addr = bBase + (uint32_t)(hl * 8192 +
                        (s * 16 + br) * 256 + ((((wn << 2) + j) ^ bSw) * 16));
                    ldsm_x2t(Bf[hl][j][0], Bf[hl][j][1], addr);
                }
            }
#pragma unroll
            for (int i = 0; i < 4; i++) {
#pragma unroll
                for (int j = 0; j < 4; j++) {
                    mma_bf16(acc[i][j], Af[0][i], Bf[0][j]);
                    mma_bf16(acc[i][j], Af[0][i], Bf[1][j]);
                    mma_bf16(acc[i][j], Af[1][i], Bf[0][j]);
                }
            }
        }
    }

    const int grp = lane >> 2;
    const int qc  = (lane & 3) * 2;
#pragma unroll
    for (int i = 0; i < 4; i++) {
#pragma unroll
        for (int j = 0; j < 4; j++) {
            int row = bm + wm * 64 + i * 16 + grp;
            int col = bn + wn * 32 + j * 8 + qc;
            float b0 = 0.f, b1 = 0.f;
            if (bias) { b0 = bias[col]; b1 = bias[col + 1]; }
            float2 v0 = make_float2(acc[i][j][0] + b0, acc[i][j][1] + b1);
            float2 v1 = make_float2(acc[i][j][2] + b0, acc[i][j][3] + b1);
            *(float2*)(C + (size_t)row * N + col)       = v0;
            *(float2*)(C + (size_t)(row + 8) * N + col) = v1;
        }
    }
}

// ---------------------------------------------------------------------------
// Tensor-core flash attention.
// Grid: (SEQ/64, BATCH*HEADS). Block: 128 threads = 4 warps, warp = 16 q rows.
// S = QK^T via split bf16 (3 MMA passes), P@V plain bf16 (1 pass), fp32 accum,
// warp-local online softmax.
// ---------------------------------------------------------------------------
__global__ __launch_bounds__(128) void attn_mma_kernel(
    const float* __restrict__ qkv, float* __restrict__ out)
{
    __shared__ uint4 sKh[64 * 8];
    __shared__ uint4 sKl[64 * 8];
    __shared__ uint4 sV [64 * 8];

    const int tid  = threadIdx.x;
    const int lane = tid & 31;
    const int warp = tid >> 5;
    const int g    = lane >> 2;     // row group 0..7
    const int t    = lane & 3;      // col group 0..3
    const int b    = blockIdx.y >> 3;
    const int h    = blockIdx.y & 7;
    const int q0   = blockIdx.x * 64;

    const float* base = qkv + (size_t)b * SEQ * QKV_N;
    const float scale = 0.125f;

    // --- Q fragments (hi/lo), per warp: rows q0+warp*16 .. +15 ---
    uint32_t Qh[4][4], Ql[4][4];
#pragma unroll
    for (int kt = 0; kt < 4; kt++) {
#pragma unroll
        for (int p = 0; p < 4; p++) {
            int row = q0 + warp * 16 + g + (p & 1) * 8;
            int col = h * DHEAD + kt * 16 + (p >> 1) * 8 + 2 * t;
            float2 f = *(const float2*)(base + (size_t)row * QKV_N + col);
            split2(f.x * scale, f.y * scale, Qh[kt][p], Ql[kt][p]);
        }
    }

    const uint32_t kbh = (uint32_t)__cvta_generic_to_shared(sKh);
    const uint32_t kbl = (uint32_t)__cvta_generic_to_shared(sKl);
    const uint32_t vb  = (uint32_t)__cvta_generic_to_shared(sV);

    float O[8][4];
#pragma unroll
    for (int j = 0; j < 8; j++)
#pragma unroll
        for (int r = 0; r < 4; r++) O[j][r] = 0.f;
    float m0 = -1e30f, m1 = -1e30f, l0 = 0.f, l1 = 0.f;

    // K ldmatrix addresses (x4, non-trans): per kt, per jpair
    const int kRowOff = (lane & 7) + ((lane >> 4) << 3);
    const int kHalf   = (lane >> 3) & 1;
    // V ldmatrix addresses (x2, trans)
    const int vRowOff = lane & 15;

    for (int kb = 0; kb < SEQ / 64; kb++) {
        // ---- load K (hi/lo) and V (hi) tiles into swizzled smem ----
        {
            int r  = tid >> 1;
            int hf = tid & 1;
            const float* krow = base + (size_t)(kb * 64 + r) * QKV_N + INNER + h * DHEAD + hf * 32;
            const float* vrow = krow + INNER;
            int sw = r & 7;
#pragma unroll
            for (int c = 0; c < 4; c++) {
                float4 f0 = *(const float4*)(krow + c * 8);
                float4 f1 = *(const float4*)(krow + c * 8 + 4);
                uint32_t h0, l0r, h1, l1r, h2, l2, h3, l3;
                split2(f0.x, f0.y, h0, l0r);
                split2(f0.z, f0.w, h1, l1r);
                split2(f1.x, f1.y, h2, l2);
                split2(f1.z, f1.w, h3, l3);
                int cc = (hf * 4 + c) ^ sw;
                sKh[r * 8 + cc] = make_uint4(h0, h1, h2, h3);
                sKl[r * 8 + cc] = make_uint4(l0r, l1r, l2, l3);
                float4 g0 = *(const float4*)(vrow + c * 8);
                float4 g1 = *(const float4*)(vrow + c * 8 + 4);
                sV[r * 8 + cc] = make_uint4(packbf2(g0.x, g0.y), packbf2(g0.z, g0.w),
                                            packbf2(g1.x, g1.y), packbf2(g1.z, g1.w));
            }
        }
        __syncthreads();

        // ---- S = QK^T (split) ----
        float S[8][4];
#pragma unroll
        for (int j = 0; j < 8; j++)
#pragma unroll
            for (int r = 0; r < 4; r++) S[j][r] = 0.f;

#pragma unroll
        for (int kt = 0; kt < 4; kt++) {
            uint32_t Bh[8][2], Bl[8][2];
#pragma unroll
            for (int jp = 0; jp < 4; jp++) {
                int row = jp * 16 + kRowOff;
                uint32_t off = (uint32_t)((row * 8 + ((2 * kt + kHalf) ^ (row & 7))) * 16);
                ldsm_x4(Bh[2 * jp][0], Bh[2 * jp][1], Bh[2 * jp + 1][0], Bh[2 * jp + 1][1],
                        kbh + off);
                ldsm_x4(Bl[2 * jp][0], Bl[2 * jp][1], Bl[2 * jp + 1][0], Bl[2 * jp + 1][1],
                        kbl + off);
            }
#pragma unroll
            for (int j = 0; j < 8; j++) {
                mma_bf16(S[j], Qh[kt], Bh[j]);
                mma_bf16(S[j], Ql[kt], Bh[j]);
                mma_bf16(S[j], Qh[kt], Bl[j]);
            }
        }

        // ---- online softmax (rows g, g+8 per lane; 4-lane groups share a row) ----
        float mx0 = -1e30f, mx1 = -1e30f;
#pragma unroll
        for (int j = 0; j < 8; j++) {
            mx0 = fmaxf(mx0, fmaxf(S[j][0], S[j][1]));
            mx1 = fmaxf(mx1, fmaxf(S[j][2], S[j][3]));
        }
        mx0 = fmaxf(mx0, __shfl_xor_sync(0xffffffffu, mx0, 1));
        mx0 = fmaxf(mx0, __shfl_xor_sync(0xffffffffu, mx0, 2));
        mx1 = fmaxf(mx1, __shfl_xor_sync(0xffffffffu, mx1, 1));
        mx1 = fmaxf(mx1, __shfl_xor_sync(0xffffffffu, mx1, 2));
        float mn0 = fmaxf(m0, mx0);
        float mn1 = fmaxf(m1, mx1);
        float a0 = __expf(m0 - mn0);
        float a1 = __expf(m1 - mn1);
        m0 = mn0; m1 = mn1;
        float s0 = 0.f, s1 = 0.f;
#pragma unroll
        for (int j = 0; j < 8; j++) {
            S[j][0] = __expf(S[j][0] - mn0);
            S[j][1] = __expf(S[j][1] - mn0);
            S[j][2] = __expf(S[j][2] - mn1);
            S[j][3] = __expf(S[j][3] - mn1);
            s0 += S[j][0] + S[j][1];
            s1 += S[j][2] + S[j][3];
        }
        s0 += __shfl_xor_sync(0xffffffffu, s0, 1);
        s0 += __shfl_xor_sync(0xffffffffu, s0, 2);
        s1 += __shfl_xor_sync(0xffffffffu, s1, 1);
        s1 += __shfl_xor_sync(0xffffffffu, s1, 2);
        l0 = l0 * a0 + s0;
        l1 = l1 * a1 + s1;
#pragma unroll
        for (int j = 0; j < 8; j++) {
            O[j][0] *= a0; O[j][1] *= a0;
            O[j][2] *= a1; O[j][3] *= a1;
        }

        // ---- pack P fragments ----
        uint32_t Pa[4][4];
#pragma unroll
        for (int kt = 0; kt < 4; kt++) {
            Pa[kt][0] = packbf2(S[2 * kt][0],     S[2 * kt][1]);
            Pa[kt][1] = packbf2(S[2 * kt][2],     S[2 * kt][3]);
            Pa[kt][2] = packbf2(S[2 * kt + 1][0], S[2 * kt + 1][1]);
            Pa[kt][3] = packbf2(S[2 * kt + 1][2], S[2 * kt + 1][3]);
        }

        // ---- O += P @ V ----
#pragma unroll
        for (int kt = 0; kt < 4; kt++) {
            uint32_t Vb[8][2];
#pragma unroll
            for (int j = 0; j < 8; j++) {
                int row = kt * 16 + vRowOff;
                uint32_t off = (uint32_t)((row * 8 + (j ^ (row & 7))) * 16);
                ldsm_x2t(Vb[j][0], Vb[j][1], vb + off);
            }
#pragma unroll
            for (int j = 0; j < 8; j++)
                mma_bf16(O[j], Pa[kt], Vb[j]);
        }
        __syncthreads();
    }

    // ---- epilogue ----
    float il0 = 1.f / l0, il1 = 1.f / l1;
    int row0 = b * SEQ + q0 + warp * 16 + g;
#pragma unroll
    for (int j = 0; j < 8; j++) {
        int col = h * DHEAD + j * 8 + 2 * t;
        *(float2*)(out + (size_t)row0 * INNER + col) =
            make_float2(O[j][0] * il0, O[j][1] * il0);
        *(float2*)(out + (size_t)(row0 + 8) * INNER + col) =
            make_float2(O[j][2] * il1, O[j][3] * il1);
    }
}

// ---------------------------------------------------------------------------
// Fused residual + LayerNorm
// ---------------------------------------------------------------------------
__global__ __launch_bounds__(128) void ln_res_kernel(
    const float* __restrict__ A, const float* __restrict__ B,
    const float* __restrict__ g, const float* __restrict__ be,
    float* __restrict__ out)
{
    const int row = blockIdx.x;
    const int tid = threadIdx.x;
    const size_t off = (size_t)row * INNER + tid * 4;

    float4 va = *(const float4*)(A + off);
    float4 vb = *(const float4*)(B + off);
    float x0 = va.x + vb.x, x1 = va.y + vb.y, x2 = va.z + vb.z, x3 = va.w + vb.w;

    float s  = x0 + x1 + x2 + x3;
    float s2 = x0 * x0 + x1 * x1 + x2 * x2 + x3 * x3;
#pragma unroll
    for (int o2 = 16; o2 >= 1; o2 >>= 1) {
        s  += __shfl_xor_sync(0xffffffffu, s,  o2);
        s2 += __shfl_xor_sync(0xffffffffu, s2, o2);
    }
    __shared__ float sh[8];
    int w = tid >> 5;
    if ((tid & 31) == 0) { sh[w] = s; sh[4 + w] = s2; }
    __syncthreads();
    s  = sh[0] + sh[1] + sh[2] + sh[3];
    s2 = sh[4] + sh[5] + sh[6] + sh[7];

    const float inv_n = 1.f / (float)INNER;
    float mu   = s * inv_n;
    float var  = s2 * inv_n - mu * mu;
    float rstd = rsqrtf(var + LN_EPS);

    float4 vg  = *(const float4*)(g  + tid * 4);
    float4 vbe = *(const float4*)(be + tid * 4);
    float4 vo;
    vo.x = (x0 - mu) * rstd * vg.x + vbe.x;
    vo.y = (x1 - mu) * rstd * vg.y + vbe.y;
    vo.z = (x2 - mu) * rstd * vg.z + vbe.z;
    vo.w = (x3 - mu) * rstd * vg.w + vbe.w;
    *(float4*)(out + off) = vo;
}

// ---------------------------------------------------------------------------
// Launch
// ---------------------------------------------------------------------------
static inline void cvt(const float* src, __nv_bfloat16* hi, __nv_bfloat16* lo, int n)
{
    int n4 = n / 4;
    cvt_split_kernel<<<(n4 + 255) / 256, 256>>>(
        (const float4*)src, (uint2*)hi, (uint2*)lo, n4);
}

extern "C" void kernel_launch(void* const* d_in, const int* in_sizes, int n_in,
                              void* d_out, int out_size)
{
    const float* x     = (const float*)d_in[0];
    const float* w_qkv = (const float*)d_in[1];
    const float* w_out = (const float*)d_in[2];
    const float* b_out = (const float*)d_in[3];
    const float* w_ff1 = (const float*)d_in[4];
    const float* w_ff2 = (const float*)d_in[5];
    const float* g1    = (const float*)d_in[6];
    const float* be1   = (const float*)d_in[7];
    const float* g2    = (const float*)d_in[8];
    const float* be2   = (const float*)d_in[9];
    float* out = (float*)d_out;

    float *qkv, *attn, *proj, *res1, *mid, *ff;
    __nv_bfloat16 *ah, *al, *bh, *bl;
    cudaGetSymbolAddress((void**)&qkv,  g_qkv);
    cudaGetSymbolAddress((void**)&attn, g_attn);
    cudaGetSymbolAddress((void**)&proj, g_proj);
    cudaGetSymbolAddress((void**)&res1, g_res1);
    cudaGetSymbolAddress((void**)&mid,  g_mid);
    cudaGetSymbolAddress((void**)&ff,   g_ff);
    cudaGetSymbolAddress((void**)&ah,   g_ah);
    cudaGetSymbolAddress((void**)&al,   g_al);
    cudaGetSymbolAddress((void**)&bh,   g_bh);
    cudaGetSymbolAddress((void**)&bl,   g_bl);

    // 1) qkv = x @ w_qkv
    cvt(x, ah, al, ROWS * INNER);
    cvt(w_qkv, bh, bl, INNER * QKV_N);
    hgemm_split_kernel<<<dim3(QKV_N / 128, ROWS / 128), 256>>>(
        ah, al, bh, bl, nullptr, qkv, ROWS, QKV_N, INNER);

    // 2) attention (tensor-core flash attention)
    attn_mma_kernel<<<dim3(SEQ / 64, BATCH * HEADS), 128>>>(qkv, attn);

    // 3) proj = attn @ w_out + b_out
    cvt(attn, ah, al, ROWS * INNER);
    cvt(w_out, bh, bl, INNER * INNER);
    hgemm_split_kernel<<<dim3(INNER / 128, ROWS / 128), 256>>>(
        ah, al, bh, bl, b_out, proj, ROWS, INNER, INNER);

    // 4) res1 = LN(x + proj)
    ln_res_kernel<<<ROWS, 128>>>(x, proj, g1, be1, res1);

    // 5) mid = res1 @ w_ff1
    cvt(res1, ah, al, ROWS * INNER);
    cvt(w_ff1, bh, bl, INNER * FF_N);
    hgemm_split_kernel<<<dim3(FF_N / 128, ROWS / 128), 256>>>(
        ah, al, bh, bl, nullptr, mid, ROWS, FF_N, INNER);

    // 6) ff = mid @ w_ff2
    cvt(mid, ah, al, ROWS * FF_N);
    cvt(w_ff2, bh, bl, FF_N * INNER);
    hgemm_split_kernel<<<dim3(INNER / 128, ROWS / 128), 256>>>(
        ah, al, bh, bl, nullptr, ff, ROWS, INNER, FF_N);

    // 7) out = LN(res1 + ff)
    ln_res_kernel<<<ROWS, 128>>>(res1, ff, g2, be2, out);
}

// round 4
// speedup vs baseline: 3.3421x; 1.1598x over previous
#include <cuda_runtime.h>
#include <cuda_bf16.h>
#include <math.h>
#include <stdint.h>

// Problem constants
#define BATCH 2
#define SEQ   2048
#define ROWS  (BATCH * SEQ)        // 4096
#define INNER 512
#define HEADS 8
#define DHEAD 64
#define QKV_N (3 * INNER)          // 1536
#define FF_N  (4 * INNER)          // 2048
#define LN_EPS 1e-6f

// ---------------------------------------------------------------------------
// Scratch (no allocations allowed -> __device__ globals)
// ---------------------------------------------------------------------------
__device__ float g_qkv [ROWS * QKV_N];
__device__ float g_proj[ROWS * INNER];
__device__ float g_res1[ROWS * INNER];
__device__ float g_ff  [ROWS * INNER];

__device__ __nv_bfloat16 g_ah [ROWS * FF_N];   // activation split hi (x/attn/res1)
__device__ __nv_bfloat16 g_al [ROWS * FF_N];   // activation split lo
__device__ __nv_bfloat16 g_ah2[ROWS * FF_N];   // mid split hi
__device__ __nv_bfloat16 g_al2[ROWS * FF_N];   // mid split lo
__device__ __nv_bfloat16 g_bh [FF_N * INNER];  // weight split hi
__device__ __nv_bfloat16 g_bl [FF_N * INNER];  // weight split lo

// ---------------------------------------------------------------------------
// Common PTX helpers
// ---------------------------------------------------------------------------
__device__ __forceinline__ void ldsm_x4(uint32_t& r0, uint32_t& r1,
                                        uint32_t& r2, uint32_t& r3, uint32_t addr)
{
    asm volatile("ldmatrix.sync.aligned.m8n8.x4.shared.b16 {%0,%1,%2,%3}, [%4];"
                 : "=r"(r0), "=r"(r1), "=r"(r2), "=r"(r3) : "r"(addr));
}
__device__ __forceinline__ void ldsm_x2t(uint32_t& r0, uint32_t& r1, uint32_t addr)
{
    asm volatile("ldmatrix.sync.aligned.m8n8.x2.trans.shared.b16 {%0,%1}, [%2];"
                 : "=r"(r0), "=r"(r1) : "r"(addr));
}
__device__ __forceinline__ void mma_bf16(float* c, const uint32_t* a, const uint32_t* b)
{
    asm volatile(
        "mma.sync.aligned.m16n8k16.row.col.f32.bf16.bf16.f32 "
        "{%0,%1,%2,%3}, {%4,%5,%6,%7}, {%8,%9}, {%0,%1,%2,%3};"
        : "+f"(c[0]), "+f"(c[1]), "+f"(c[2]), "+f"(c[3])
        : "r"(a[0]), "r"(a[1]), "r"(a[2]), "r"(a[3]), "r"(b[0]), "r"(b[1]));
}
__device__ __forceinline__ uint32_t packbf2(float a, float b)
{
    __nv_bfloat162 t = __floats2bfloat162_rn(a, b);
    return *reinterpret_cast<uint32_t*>(&t);
}
__device__ __forceinline__ void split2(float a, float b, uint32_t& hi, uint32_t& lo)
{
    __nv_bfloat16 ha = __float2bfloat16(a);
    __nv_bfloat16 hb = __float2bfloat16(b);
    __nv_bfloat16 la = __float2bfloat16(a - __bfloat162float(ha));
    __nv_bfloat16 lb = __float2bfloat16(b - __bfloat162float(hb));
    __nv_bfloat162 H; H.x = ha; H.y = hb;
    __nv_bfloat162 L; L.x = la; L.y = lb;
    hi = *reinterpret_cast<uint32_t*>(&H);
    lo = *reinterpret_cast<uint32_t*>(&L);
}

// ---------------------------------------------------------------------------
// fp32 -> (hi, lo) bf16 split (bulk, for x and weights)
// ---------------------------------------------------------------------------
__global__ __launch_bounds__(256) void cvt_split_kernel(
    const float4* __restrict__ x, uint2* __restrict__ hi, uint2* __restrict__ lo,
    int n4)
{
    int i = blockIdx.x * blockDim.x + threadIdx.x;
    if (i >= n4) return;
    float4 v = x[i];
    union { __nv_bfloat16 b[4]; uint2 u; } H, L;
    H.b[0] = __float2bfloat16(v.x);
    H.b[1] = __float2bfloat16(v.y);
    H.b[2] = __float2bfloat16(v.z);
    H.b[3] = __float2bfloat16(v.w);
    L.b[0] = __float2bfloat16(v.x - __bfloat162float(H.b[0]));
    L.b[1] = __float2bfloat16(v.y - __bfloat162float(H.b[1]));
    L.b[2] = __float2bfloat16(v.z - __bfloat162float(H.b[2]));
    L.b[3] = __float2bfloat16(v.w - __bfloat162float(H.b[3]));
    hi[i] = H.u;
    lo[i] = L.u;
}

// ---------------------------------------------------------------------------
// Tensor-core split-bf16 GEMM.
// Output: fp32 C (optional) and/or split bf16 (Chi/Clo, optional).
// ---------------------------------------------------------------------------
__global__ __launch_bounds__(256) void hgemm_split_kernel(
    const __nv_bfloat16* __restrict__ Ah, const __nv_bfloat16* __restrict__ Al,
    const __nv_bfloat16* __restrict__ Bh, const __nv_bfloat16* __restrict__ Bl,
    const float* __restrict__ bias, float* __restrict__ C,
    __nv_bfloat16* __restrict__ Chi, __nv_bfloat16* __restrict__ Clo,
    int M, int N, int K)
{
    __shared__ uint4 sA[2][512];
    __shared__ uint4 sB[2][512];

    const int tid  = threadIdx.x;
    const int lane = tid & 31;
    const int warp = tid >> 5;
    const int wm   = warp >> 2;
    const int wn   = warp & 3;
    const int bm   = blockIdx.y * 128;
    const int bn   = blockIdx.x * 128;

    const int arow = tid >> 2;
    const int ach  = tid & 3;
    const int brow = tid >> 4;
    const int bch  = tid & 15;

    const int aSwS = ach ^ ((arow >> 1) & 3);
    const int bSwS = bch ^ (brow & 7);

    const uint32_t aBase = (uint32_t)__cvta_generic_to_shared(&sA[0][0]);
    const uint32_t bBase = (uint32_t)__cvta_generic_to_shared(&sB[0][0]);
    const int ar   = wm * 64 + (lane & 15);
    const int aSw  = (ar >> 1) & 3;
    const int aHi  = lane >> 4;
    const int br   = lane & 15;
    const int bSw  = br & 7;

    float acc[4][4][4];
#pragma unroll
    for (int i = 0; i < 4; i++)
#pragma unroll
        for (int j = 0; j < 4; j++)
#pragma unroll
            for (int r = 0; r < 4; r++) acc[i][j][r] = 0.f;

    uint4 rA[2][2], rB[2][2];
    {
        const int kk = 0;
        rA[0][0] = *(const uint4*)(Ah + (size_t)(bm + arow)      * K + kk + ach * 8);
        rA[0][1] = *(const uint4*)(Ah + (size_t)(bm + arow + 64) * K + kk + ach * 8);
        rA[1][0] = *(const uint4*)(Al + (size_t)(bm + arow)      * K + kk + ach * 8);
        rA[1][1] = *(const uint4*)(Al + (size_t)(bm + arow + 64) * K + kk + ach * 8);
        rB[0][0] = *(const uint4*)(Bh + (size_t)(kk + brow)      * N + bn + bch * 8);
        rB[0][1] = *(const uint4*)(Bh + (size_t)(kk + brow + 16) * N + bn + bch * 8);
        rB[1][0] = *(const uint4*)(Bl + (size_t)(kk + brow)      * N + bn + bch * 8);
        rB[1][1] = *(const uint4*)(Bl + (size_t)(kk + brow + 16) * N + bn + bch * 8);
    }

    const int sa0 = arow * 4 + aSwS;
    const int sa1 = (arow + 64) * 4 + aSwS;
    const int sb0 = brow * 16 + bSwS;
    const int sb1 = (brow + 16) * 16 + bSwS;

    for (int k0 = 0; k0 < K; k0 += 32) {
        __syncthreads();
        sA[0][sa0] = rA[0][0]; sA[0][sa1] = rA[0][1];
        sA[1][sa0] = rA[1][0]; sA[1][sa1] = rA[1][1];
        sB[0][sb0] = rB[0][0]; sB[0][sb1] = rB[0][1];
        sB[1][sb0] = rB[1][0]; sB[1][sb1] = rB[1][1];
        __syncthreads();

        {
            int kk = k0 + 32; if (kk >= K) kk = 0;
            rA[0][0] = *(const uint4*)(Ah + (size_t)(bm + arow)      * K + kk + ach * 8);
            rA[0][1] = *(const uint4*)(Ah + (size_t)(bm + arow + 64) * K + kk + ach * 8);
            rA[1][0] = *(const uint4*)(Al + (size_t)(bm + arow)      * K + kk + ach * 8);
            rA[1][1] = *(const uint4*)(Al + (size_t)(bm + arow + 64) * K + kk + ach * 8);
            rB[0][0] = *(const uint4*)(Bh + (size_t)(kk + brow)      * N + bn + bch * 8);
            rB[0][1] = *(const uint4*)(Bh + (size_t)(kk + brow + 16) * N + bn + bch * 8);
            rB[1][0] = *(const uint4*)(Bl + (size_t)(kk + brow)      * N + bn + bch * 8);
            rB[1][1] = *(const uint4*)(Bl + (size_t)(kk + brow + 16) * N + bn + bch * 8);
        }

#pragma unroll
        for (int s = 0; s < 2; s++) {
            uint32_t Af[2][4][4];
            uint32_t Bf[2][4][2];
#pragma unroll
            for (int hl = 0; hl < 2; hl++) {
#pragma unroll
                for (int i = 0; i < 4; i++) {
                    uint32_t addr = aBase + (uint32_t)(hl * 8192 +
                        (ar + i * 16) * 64 + (((2 * s + aHi) ^ aSw) * 16));
                    ldsm_x4(Af[hl][i][0], Af[hl][i][1], Af[hl][i][2], Af[hl][i][3], addr);
                }
#pragma unroll
                for (int j = 0; j < 4; j++) {
                    uint32_t addr = bBase + (uint32_t)(hl * 8192 +
                        (s * 16 + br) * 256 + ((((wn << 2) + j) ^ bSw) * 16));
                    ldsm_x2t(Bf[hl][j][0], Bf[hl][j][1], addr);
                }
            }
#pragma unroll
            for (int i = 0; i < 4; i++) {
#pragma unroll
                for (int j = 0; j < 4; j++) {
                    mma_bf16(acc[i][j], Af[0][i], Bf[0][j]);
                    mma_bf16(acc[i][j], Af[0][i], Bf[1][j]);
                    mma_bf16(acc[i][j], Af[1][i], Bf[0][j]);
                }
            }
        }
    }

    const int grp = lane >> 2;
    const int qc  = (lane & 3) * 2;
#pragma unroll
    for (int i = 0; i < 4; i++) {
#pragma unroll
        for (int j = 0; j < 4; j++) {
            int row = bm + wm * 64 + i * 16 + grp;
            int col = bn + wn * 32 + j * 8 + qc;
            float b0 = 0.f, b1 = 0.f;
            if (bias) { b0 = bias[col]; b1 = bias[col + 1]; }
            float v00 = acc[i][j][0] + b0, v01 = acc[i][j][1] + b1;
            float v10 = acc[i][j][2] + b0, v11 = acc[i][j][3] + b1;
            if (C) {
                *(float2*)(C + (size_t)row * N + col)       = make_float2(v00, v01);
                *(float2*)(C + (size_t)(row + 8) * N + col) = make_float2(v10, v11);
            }
            if (Chi) {
                uint32_t h0, l0, h1, l1;
                split2(v00, v01, h0, l0);
                split2(v10, v11, h1, l1);
                *(uint32_t*)(Chi + (size_t)row * N + col)       = h0;
                *(uint32_t*)(Clo + (size_t)row * N + col)       = l0;
                *(uint32_t*)(Chi + (size_t)(row + 8) * N + col) = h1;
                *(uint32_t*)(Clo + (size_t)(row + 8) * N + col) = l1;
            }
        }
    }
}

// ---------------------------------------------------------------------------
// Tensor-core flash attention, 32 query rows per warp.
// Grid: (SEQ/128, BATCH*HEADS). Block: 128 threads = 4 warps x 32 rows.
// Output written directly as split bf16 (hi/lo) for the next GEMM.
// ---------------------------------------------------------------------------
__global__ __launch_bounds__(128) void attn_mma_kernel(
    const float* __restrict__ qkv,
    __nv_bfloat16* __restrict__ outHi, __nv_bfloat16* __restrict__ outLo)
{
    __shared__ uint4 sKh[64 * 8];
    __shared__ uint4 sKl[64 * 8];
    __shared__ uint4 sV [64 * 8];

    const int tid  = threadIdx.x;
    const int lane = tid & 31;
    const int warp = tid >> 5;
    const int g    = lane >> 2;
    const int t    = lane & 3;
    const int b    = blockIdx.y >> 3;
    const int h    = blockIdx.y & 7;
    const int q0   = blockIdx.x * 128;

    const float* base = qkv + (size_t)b * SEQ * QKV_N;
    const float scale = 0.125f;

    // --- Q fragments (hi/lo), per warp: 2 x 16 rows ---
    uint32_t Qh[2][4][4], Ql[2][4][4];
#pragma unroll
    for (int u = 0; u < 2; u++) {
#pragma unroll
        for (int kt = 0; kt < 4; kt++) {
#pragma unroll
            for (int p = 0; p < 4; p++) {
                int row = q0 + warp * 32 + u * 16 + g + (p & 1) * 8;
                int col = h * DHEAD + kt * 16 + (p >> 1) * 8 + 2 * t;
                float2 f = *(const float2*)(base + (size_t)row * QKV_N + col);
                split2(f.x * scale, f.y * scale, Qh[u][kt][p], Ql[u][kt][p]);
            }
        }
    }

    const uint32_t kbh = (uint32_t)__cvta_generic_to_shared(sKh);
    const uint32_t kbl = (uint32_t)__cvta_generic_to_shared(sKl);
    const uint32_t vb  = (uint32_t)__cvta_generic_to_shared(sV);

    float O[2][8][4];
#pragma unroll
    for (int u = 0; u < 2; u++)
#pragma unroll
        for (int j = 0; j < 8; j++)
#pragma unroll
            for (int r = 0; r < 4; r++) O[u][j][r] = 0.f;
    float m[2][2], l[2][2];
#pragma unroll
    for (int u = 0; u < 2; u++) { m[u][0] = m[u][1] = -1e30f; l[u][0] = l[u][1] = 0.f; }

    const int kRowOff = (lane & 7) + ((lane >> 4) << 3);
    const int kHalf   = (lane >> 3) & 1;
    const int vRowOff = lane & 15;

    for (int kb = 0; kb < SEQ / 64; kb++) {
        // ---- load K (hi/lo) and V tiles into swizzled smem ----
        {
            int r  = tid >> 1;
            int hf = tid & 1;
            const float* krow = base + (size_t)(kb * 64 + r) * QKV_N + INNER + h * DHEAD + hf * 32;
            const float* vrow = krow + INNER;
            int sw = r & 7;
#pragma unroll
            for (int c = 0; c < 4; c++) {
                float4 f0 = *(const float4*)(krow + c * 8);
                float4 f1 = *(const float4*)(krow + c * 8 + 4);
                uint32_t h0, l0r, h1, l1r, h2, l2r, h3, l3r;
                split2(f0.x, f0.y, h0, l0r);
                split2(f0.z, f0.w, h1, l1r);
                split2(f1.x, f1.y, h2, l2r);
                split2(f1.z, f1.w, h3, l3r);
                int cc = (hf * 4 + c) ^ sw;
                sKh[r * 8 + cc] = make_uint4(h0, h1, h2, h3);
                sKl[r * 8 + cc] = make_uint4(l0r, l1r, l2r, l3r);
                float4 g0 = *(const float4*)(vrow + c * 8);
                float4 g1 = *(const float4*)(vrow + c * 8 + 4);
                sV[r * 8 + cc] = make_uint4(packbf2(g0.x, g0.y), packbf2(g0.z, g0.w),
                                            packbf2(g1.x, g1.y), packbf2(g1.z, g1.w));
            }
        }
        __syncthreads();

        // ---- S = QK^T (split) for both row halves ----
        float S[2][8][4];
#pragma unroll
        for (int u = 0; u < 2; u++)
#pragma unroll
            for (int j = 0; j < 8; j++)
#pragma unroll
                for (int r = 0; r < 4; r++) S[u][j][r] = 0.f;

#pragma unroll
        for (int kt = 0; kt < 4; kt++) {
            uint32_t Bh[8][2], Bl[8][2];
#pragma unroll
            for (int jp = 0; jp < 4; jp++) {
                int row = jp * 16 + kRowOff;
                uint32_t off = (uint32_t)((row * 8 + ((2 * kt + kHalf) ^ (row & 7))) * 16);
                ldsm_x4(Bh[2 * jp][0], Bh[2 * jp][1], Bh[2 * jp + 1][0], Bh[2 * jp + 1][1],
                        kbh + off);
                ldsm_x4(Bl[2 * jp][0], Bl[2 * jp][1], Bl[2 * jp + 1][0], Bl[2 * jp + 1][1],
                        kbl + off);
            }
#pragma unroll
            for (int j = 0; j < 8; j++) {
#pragma unroll
                for (int u = 0; u < 2; u++) {
                    mma_bf16(S[u][j], Qh[u][kt], Bh[j]);
                    mma_bf16(S[u][j], Ql[u][kt], Bh[j]);
                    mma_bf16(S[u][j], Qh[u][kt], Bl[j]);
                }
            }
        }

        // ---- online softmax + P packing, per row half ----
        uint32_t Pa[2][4][4];
#pragma unroll
        for (int u = 0; u < 2; u++) {
            float mx0 = -1e30f, mx1 = -1e30f;
#pragma unroll
            for (int j = 0; j < 8; j++) {
                mx0 = fmaxf(mx0, fmaxf(S[u][j][0], S[u][j][1]));
                mx1 = fmaxf(mx1, fmaxf(S[u][j][2], S[u][j][3]));
            }
            mx0 = fmaxf(mx0, __shfl_xor_sync(0xffffffffu, mx0, 1));
            mx0 = fmaxf(mx0, __shfl_xor_sync(0xffffffffu, mx0, 2));
            mx1 = fmaxf(mx1, __shfl_xor_sync(0xffffffffu, mx1, 1));
            mx1 = fmaxf(mx1, __shfl_xor_sync(0xffffffffu, mx1, 2));
            float mn0 = fmaxf(m[u][0], mx0);
            float mn1 = fmaxf(m[u][1], mx1);
            float a0 = __expf(m[u][0] - mn0);
            float a1 = __expf(m[u][1] - mn1);
            m[u][0] = mn0; m[u][1] = mn1;
            float s0 = 0.f, s1 = 0.f;
#pragma unroll
            for (int j = 0; j < 8; j++) {
                S[u][j][0] = __expf(S[u][j][0] - mn0);
                S[u][j][1] = __expf(S[u][j][1] - mn0);
                S[u][j][2] = __expf(S[u][j][2] - mn1);
                S[u][j][3] = __expf(S[u][j][3] - mn1);
                s0 += S[u][j][0] + S[u][j][1];
                s1 += S[u][j][2] + S[u][j][3];
            }
            s0 += __shfl_xor_sync(0xffffffffu, s0, 1);
            s0 += __shfl_xor_sync(0xffffffffu, s0, 2);
            s1 += __shfl_xor_sync(0xffffffffu, s1, 1);
            s1 += __shfl_xor_sync(0xffffffffu, s1, 2);
            l[u][0] = l[u][0] * a0 + s0;
            l[u][1] = l[u][1] * a1 + s1;
#pragma unroll
            for (int j = 0; j < 8; j++) {
                O[u][j][0] *= a0; O[u][j][1] *= a0;
                O[u][j][2] *= a1; O[u][j][3] *= a1;
            }
#pragma unroll
            for (int kt = 0; kt < 4; kt++) {
                Pa[u][kt][0] = packbf2(S[u][2 * kt][0],     S[u][2 * kt][1]);
                Pa[u][kt][1] = packbf2(S[u][2 * kt][2],     S[u][2 * kt][3]);
                Pa[u][kt][2] = packbf2(S[u][2 * kt + 1][0], S[u][2 * kt + 1][1]);
                Pa[u][kt][3] = packbf2(S[u][2 * kt + 1][2], S[u][2 * kt + 1][3]);
            }
        }

        // ---- O += P @ V ----
#pragma unroll
        for (int kt = 0; kt < 4; kt++) {
            uint32_t Vb[8][2];
#pragma unroll
            for (int j = 0; j < 8; j++) {
                int row = kt * 16 + vRowOff;
                uint32_t off = (uint32_t)((row * 8 + (j ^ (row & 7))) * 16);
                ldsm_x2t(Vb[j][0], Vb[j][1], vb + off);
            }
#pragma unroll
            for (int j = 0; j < 8; j++) {
                mma_bf16(O[0][j], Pa[0][kt], Vb[j]);
                mma_bf16(O[1][j], Pa[1][kt], Vb[j]);
            }
        }
        __syncthreads();
    }

    // ---- epilogue: normalize, split to hi/lo bf16 ----
#pragma unroll
    for (int u = 0; u < 2; u++) {
        float il0 = 1.f / l[u][0], il1 = 1.f / l[u][1];
        int row0 = b * SEQ + q0 + warp * 32 + u * 16 + g;
#pragma unroll
        for (int j = 0; j < 8; j++) {
            int col = h * DHEAD + j * 8 + 2 * t;
            uint32_t h0, l0r, h1, l1r;
            split2(O[u][j][0] * il0, O[u][j][1] * il0, h0, l0r);
            split2(O[u][j][2] * il1, O[u][j][3] * il1, h1, l1r);
            *(uint32_t*)(outHi + (size_t)row0 * INNER + col)       = h0;
            *(uint32_t*)(outLo + (size_t)row0 * INNER + col)       = l0r;
            *(uint32_t*)(outHi + (size_t)(row0 + 8) * INNER + col) = h1;
            *(uint32_t*)(outLo + (size_t)(row0 + 8) * INNER + col) = l1r;
        }
    }
}

// ---------------------------------------------------------------------------
// Fused residual + LayerNorm (+ optional split bf16 output)
// ---------------------------------------------------------------------------
__global__ __launch_bounds__(128) void ln_res_kernel(
    const float* __restrict__ A, const float* __restrict__ B,
    const float* __restrict__ g, const float* __restrict__ be,
    float* __restrict__ out,
    __nv_bfloat16* __restrict__ outHi, __nv_bfloat16* __restrict__ outLo)
{
    const int row = blockIdx.x;
    const int tid = threadIdx.x;
    const size_t off = (size_t)row * INNER + tid * 4;

    float4 va = *(const float4*)(A + off);
    float4 vb = *(const float4*)(B + off);
    float x0 = va.x + vb.x, x1 = va.y + vb.y, x2 = va.z + vb.z, x3 = va.w + vb.w;

    float s  = x0 + x1 + x2 + x3;
    float s2 = x0 * x0 + x1 * x1 + x2 * x2 + x3 * x3;
#pragma unroll
    for (int o2 = 16; o2 >= 1; o2 >>= 1) {
        s  += __shfl_xor_sync(0xffffffffu, s,  o2);
        s2 += __shfl_xor_sync(0xffffffffu, s2, o2);
    }
    __shared__ float sh[8];
    int w = tid >> 5;
    if ((tid & 31) == 0) { sh[w] = s; sh[4 + w] = s2; }
    __syncthreads();
    s  = sh[0] + sh[1] + sh[2] + sh[3];
    s2 = sh[4] + sh[5] + sh[6] + sh[7];

    const float inv_n = 1.f / (float)INNER;
    float mu   = s * inv_n;
    float var  = s2 * inv_n - mu * mu;
    float rstd = rsqrtf(var + LN_EPS);

    float4 vg  = *(const float4*)(g  + tid * 4);
    float4 vbe = *(const float4*)(be + tid * 4);
    float4 vo;
    vo.x = (x0 - mu) * rstd * vg.x + vbe.x;
    vo.y = (x1 - mu) * rstd * vg.y + vbe.y;
    vo.z = (x2 - mu) * rstd * vg.z + vbe.z;
    vo.w = (x3 - mu) * rstd * vg.w + vbe.w;
    *(float4*)(out + off) = vo;

    if (outHi) {
        uint32_t h0, l0r, h1, l1r;
        split2(vo.x, vo.y, h0, l0r);
        split2(vo.z, vo.w, h1, l1r);
        *(uint2*)(outHi + off) = make_uint2(h0, h1);
        *(uint2*)(outLo + off) = make_uint2(l0r, l1r);
    }
}

// ---------------------------------------------------------------------------
// Launch
// ---------------------------------------------------------------------------
static inline void cvt(const float* src, __nv_bfloat16* hi, __nv_bfloat16* lo, int n)
{
    int n4 = n / 4;
    cvt_split_kernel<<<(n4 + 255) / 256, 256>>>(
        (const float4*)src, (uint2*)hi, (uint2*)lo, n4);
}

extern "C" void kernel_launch(void* const* d_in, const int* in_sizes, int n_in,
                              void* d_out, int out_size)
{
    const float* x     = (const float*)d_in[0];
    const float* w_qkv = (const float*)d_in[1];
    const float* w_out = (const float*)d_in[2];
    const float* b_out = (const float*)d_in[3];
    const float* w_ff1 = (const float*)d_in[4];
    const float* w_ff2 = (const float*)d_in[5];
    const float* g1    = (const float*)d_in[6];
    const float* be1   = (const float*)d_in[7];
    const float* g2    = (const float*)d_in[8];
    const float* be2   = (const float*)d_in[9];
    float* out = (float*)d_out;

    float *qkv, *proj, *res1, *ff;
    __nv_bfloat16 *ah, *al, *ah2, *al2, *bh, *bl;
    cudaGetSymbolAddress((void**)&qkv,  g_qkv);
    cudaGetSymbolAddress((void**)&proj, g_proj);
    cudaGetSymbolAddress((void**)&res1, g_res1);
    cudaGetSymbolAddress((void**)&ff,   g_ff);
    cudaGetSymbolAddress((void**)&ah,   g_ah);
    cudaGetSymbolAddress((void**)&al,   g_al);
    cudaGetSymbolAddress((void**)&ah2,  g_ah2);
    cudaGetSymbolAddress((void**)&al2,  g_al2);
    cudaGetSymbolAddress((void**)&bh,   g_bh);
    cudaGetSymbolAddress((void**)&bl,   g_bl);

    // 1) qkv = x @ w_qkv
    cvt(x, ah, al, ROWS * INNER);
    cvt(w_qkv, bh, bl, INNER * QKV_N);
    hgemm_split_kernel<<<dim3(QKV_N / 128, ROWS / 128), 256>>>(
        ah, al, bh, bl, nullptr, qkv, nullptr, nullptr, ROWS, QKV_N, INNER);

    // 2) attention -> split bf16 directly into ah/al
    attn_mma_kernel<<<dim3(SEQ / 128, BATCH * HEADS), 128>>>(qkv, ah, al);

    // 3) proj = attn @ w_out + b_out
    cvt(w_out, bh, bl, INNER * INNER);
    hgemm_split_kernel<<<dim3(INNER / 128, ROWS / 128), 256>>>(
        ah, al, bh, bl, b_out, proj, nullptr, nullptr, ROWS, INNER, INNER);

    // 4) res1 = LN(x + proj), also emit split bf16 into ah/al
    ln_res_kernel<<<ROWS, 128>>>(x, proj, g1, be1, res1, ah, al);

    // 5) mid = res1 @ w_ff1 -> split bf16 directly into ah2/al2
    cvt(w_ff1, bh, bl, INNER * FF_N);
    hgemm_split_kernel<<<dim3(FF_N / 128, ROWS / 128), 256>>>(
        ah, al, bh, bl, nullptr, nullptr, ah2, al2, ROWS, FF_N, INNER);

    // 6) ff = mid @ w_ff2
    cvt(w_ff2, bh, bl, FF_N * INNER);
    hgemm_split_kernel<<<dim3(INNER / 128, ROWS / 128), 256>>>(
        ah2, al2, bh, bl, nullptr, ff, nullptr, nullptr, ROWS, INNER, FF_N);

    // 7) out = LN(res1 + ff)
    ln_res_kernel<<<ROWS, 128>>>(res1, ff, g2, be2, out, nullptr, nullptr);
}